// round 2
// baseline (speedup 1.0000x reference)
#include <cuda_runtime.h>
#include <cuda_bf16.h>

// ---------------- problem constants ----------------
#define HID 512
#define MID 256
#define COND_D 256
#define OP_D 32
#define EX_D 32
#define LL 16
#define NN 1024
#define TT 8
#define BB (LL*NN)          // 16384
#define G4 (4*HID)          // 2048
#define IN2 (OP_D+EX_D+MID) // 320

// ---------------- scratch (device globals; no allocation allowed) ----------------
__device__ float g_h1[BB*HID];
__device__ float g_c1[BB*HID];
__device__ float g_gates[BB*G4];
__device__ float g_last[BB*MID];
__device__ float g_cat[BB*IN2];
__device__ float g_xp2[(long)BB*G4];
__device__ float g_ph[(NN+1)*HID];
__device__ float g_pc[(NN+1)*HID];
__device__ float g_hin[NN*HID];
__device__ float g_cin[NN*HID];
__device__ float g_bs1[G4];
__device__ float g_bs2[G4];
__device__ float g_mu[HID];
__device__ float g_rstd[HID];
__device__ int   g_map32[LL*NN*2];
__device__ int   g_map_is64;

// ---------------- SGEMM: C = [acc?C:0] + A(MxK, lda) @ B(NxK)^T (+bias) [relu] ----------------
#define FLAG_ACC  1
#define FLAG_RELU 2
#define BM 128
#define BN 128
#define BK 8

__global__ __launch_bounds__(256) void sgemm_bt(
    const float* __restrict__ A, int lda,
    const float* __restrict__ B,            // [N,K] row-major
    const float* __restrict__ bias,         // [N] or null
    float* __restrict__ C,                  // [M,N]
    int M, int N, int K, int flags)
{
    __shared__ float As[BK][BM];
    __shared__ float Bs[BK][BN];
    int tid = threadIdx.x;
    int n0 = blockIdx.x * BN;
    int m0 = blockIdx.y * BM;
    int tx = tid & 15;
    int ty = tid >> 4;

    float acc[8][8];
    #pragma unroll
    for (int i = 0; i < 8; i++)
        #pragma unroll
        for (int j = 0; j < 8; j++) acc[i][j] = 0.f;

    int lr = tid >> 1;          // 0..127
    int lk = (tid & 1) * 4;     // 0 or 4
    const float* Ab = A + (long)(m0 + lr) * lda + lk;
    const float* Bb = B + (long)(n0 + lr) * K + lk;

    for (int k0 = 0; k0 < K; k0 += BK) {
        float4 av = *(const float4*)(Ab + k0);
        float4 bv = *(const float4*)(Bb + k0);
        As[lk+0][lr] = av.x; As[lk+1][lr] = av.y; As[lk+2][lr] = av.z; As[lk+3][lr] = av.w;
        Bs[lk+0][lr] = bv.x; Bs[lk+1][lr] = bv.y; Bs[lk+2][lr] = bv.z; Bs[lk+3][lr] = bv.w;
        __syncthreads();
        #pragma unroll
        for (int kk = 0; kk < BK; kk++) {
            float4 a0 = *(const float4*)&As[kk][ty*4];
            float4 a1 = *(const float4*)&As[kk][64 + ty*4];
            float4 b0 = *(const float4*)&Bs[kk][tx*4];
            float4 b1 = *(const float4*)&Bs[kk][64 + tx*4];
            float ar[8] = {a0.x,a0.y,a0.z,a0.w, a1.x,a1.y,a1.z,a1.w};
            float br[8] = {b0.x,b0.y,b0.z,b0.w, b1.x,b1.y,b1.z,b1.w};
            #pragma unroll
            for (int i = 0; i < 8; i++)
                #pragma unroll
                for (int j = 0; j < 8; j++)
                    acc[i][j] += ar[i] * br[j];
        }
        __syncthreads();
    }

    #pragma unroll
    for (int i = 0; i < 8; i++) {
        int row = m0 + ((i < 4) ? (ty*4 + i) : (64 + ty*4 + i - 4));
        float* Crow = C + (long)row * N;
        #pragma unroll
        for (int j = 0; j < 8; j++) {
            int col = n0 + ((j < 4) ? (tx*4 + j) : (64 + tx*4 + j - 4));
            float v = acc[i][j];
            if (bias) v += bias[col];
            if (flags & FLAG_ACC) v += Crow[col];
            if (flags & FLAG_RELU) v = fmaxf(v, 0.f);
            Crow[col] = v;
        }
    }
}

// ---------------- mapping dtype normalization ----------------
// Reference builds mapping via randint(int32).astype(int64); the harness may
// hand it to us as either int32 or int64. Detect by reinterpreting the first
// 1024 values as int64: genuine int64 values are all in [0, NN]; int32 data
// reinterpreted as int64 is lo|hi<<32 with hi mostly nonzero -> huge.
__global__ void detect_map(const long long* __restrict__ raw) {
    if (threadIdx.x == 0 && blockIdx.x == 0) {
        int ok = 1;
        for (int i = 0; i < 1024; i++) {
            long long v = raw[i];
            if (v < 0 || v > NN) { ok = 0; break; }
        }
        g_map_is64 = ok;
    }
}

__global__ void convert_map(const void* __restrict__ raw, int* __restrict__ o) {
    int i = blockIdx.x * blockDim.x + threadIdx.x;
    if (i >= LL*NN*2) return;
    if (g_map_is64) o[i] = (int)((const long long*)raw)[i];
    else            o[i] = ((const int*)raw)[i];
}

// ---------------- elementwise kernels ----------------
__device__ __forceinline__ float sigf(float x) { return 1.f / (1.f + expf(-x)); }

__global__ void vec_add2(float* o, const float* a, const float* b, int n) {
    int i = blockIdx.x * blockDim.x + threadIdx.x;
    if (i < n) o[i] = a[i] + b[i];
}

// LSTM cell for phase-1 (B=16384): gates[b,2048] -> h,c in place
__global__ void lstm_cell1(const float* __restrict__ gates,
                           float* __restrict__ h, float* __restrict__ c) {
    long idx = (long)blockIdx.x * blockDim.x + threadIdx.x;
    if (idx >= (long)BB * HID) return;
    int b = (int)(idx >> 9), j = (int)(idx & 511);
    const float* g = gates + (long)b * G4;
    float ig = sigf(g[j]);
    float fg = sigf(g[HID + j]);
    float gg = tanhf(g[2*HID + j]);
    float og = sigf(g[3*HID + j]);
    float cn = fg * c[idx] + ig * gg;
    c[idx] = cn;
    h[idx] = og * tanhf(cn);
}

// LSTM cell for tree phase (N=1024): reads cin, writes into padded ph/pc rows 1..N
__global__ void lstm_cell2(const float* __restrict__ gates,
                           const float* __restrict__ cin,
                           float* __restrict__ ph, float* __restrict__ pc) {
    int idx = blockIdx.x * blockDim.x + threadIdx.x;
    if (idx >= NN * HID) return;
    int b = idx >> 9, j = idx & 511;
    const float* g = gates + (long)b * G4;
    float ig = sigf(g[j]);
    float fg = sigf(g[HID + j]);
    float gg = tanhf(g[2*HID + j]);
    float og = sigf(g[3*HID + j]);
    float cn = fg * cin[idx] + ig * gg;
    pc[(b + 1) * HID + j] = cn;
    ph[(b + 1) * HID + j] = og * tanhf(cn);
}

// children gather: hin = 0.5*(ph[m0]+ph[m1]) etc.  (mapping values in [0, NN])
__global__ void gather_children(const int* __restrict__ mp,
                                const float* __restrict__ ph, const float* __restrict__ pc,
                                float* __restrict__ hin, float* __restrict__ cin) {
    int idx = blockIdx.x * blockDim.x + threadIdx.x;
    if (idx >= NN * HID) return;
    int n = idx >> 9, j = idx & 511;
    int a = mp[n*2 + 0];
    int b = mp[n*2 + 1];
    // clamp defensively (values should already be in [0, NN])
    a = min(max(a, 0), NN);
    b = min(max(b, 0), NN);
    hin[idx] = 0.5f * (ph[a * HID + j] + ph[b * HID + j]);
    cin[idx] = 0.5f * (pc[a * HID + j] + pc[b * HID + j]);
}

// concat [ops | extra | last] -> cat [BB, 320]
__global__ void concat_in2(const float* __restrict__ ops, const float* __restrict__ ex,
                           const float* __restrict__ last, float* __restrict__ cat) {
    long idx = (long)blockIdx.x * blockDim.x + threadIdx.x;
    if (idx >= (long)BB * IN2) return;
    int r = (int)(idx / IN2), k = (int)(idx % IN2);
    float v;
    if (k < OP_D)            v = ops[(long)r * OP_D + k];
    else if (k < OP_D+EX_D)  v = ex[(long)r * EX_D + (k - OP_D)];
    else                     v = last[(long)r * MID + (k - OP_D - EX_D)];
    cat[idx] = v;
}

// batchnorm stats: block = (32,8), grid = C/32
__global__ void bn_stats(const float* __restrict__ X, int Brows, int C,
                         float* __restrict__ mu, float* __restrict__ rstd) {
    int c = blockIdx.x * 32 + threadIdx.x;
    float s = 0.f, s2 = 0.f;
    for (int r = threadIdx.y; r < Brows; r += 8) {
        float v = X[(long)r * C + c];
        s += v; s2 += v * v;
    }
    __shared__ float sh[8][33], sh2[8][33];
    sh[threadIdx.y][threadIdx.x] = s;
    sh2[threadIdx.y][threadIdx.x] = s2;
    __syncthreads();
    if (threadIdx.y == 0) {
        #pragma unroll
        for (int y = 1; y < 8; y++) { s += sh[y][threadIdx.x]; s2 += sh2[y][threadIdx.x]; }
        float m = s / (float)Brows;
        float var = s2 / (float)Brows - m * m;
        mu[c] = m;
        rstd[c] = rsqrtf(var + 1e-5f);
    }
}

__global__ void bn_apply(const float* __restrict__ X,
                         const float* __restrict__ mu, const float* __restrict__ rstd,
                         const float* __restrict__ gam, const float* __restrict__ bet,
                         float* __restrict__ Y, long total, int C) {
    long idx = (long)blockIdx.x * blockDim.x + threadIdx.x;
    if (idx >= total) return;
    int c = (int)(idx % C);
    Y[idx] = gam[c] * (X[idx] - mu[c]) * rstd[c] + bet[c];
}

// ---------------- launch ----------------
extern "C" void kernel_launch(void* const* d_in, const int* in_sizes, int n_in,
                              void* d_out, int out_size) {
    const float* ops   = (const float*)d_in[0];
    const float* extra = (const float*)d_in[1];
    const float* cond  = (const float*)d_in[2];
    // d_in[3] condition_masks: unused by reference (all ones)
    const void*  mapping_raw = d_in[4];
    const float* W1ih = (const float*)d_in[5];
    const float* W1hh = (const float*)d_in[6];
    const float* b1ih = (const float*)d_in[7];
    const float* b1hh = (const float*)d_in[8];
    const float* condW = (const float*)d_in[9];
    const float* condb = (const float*)d_in[10];
    const float* bn1g = (const float*)d_in[11];
    const float* bn1b = (const float*)d_in[12];
    const float* W2ih = (const float*)d_in[13];
    const float* W2hh = (const float*)d_in[14];
    const float* b2ih = (const float*)d_in[15];
    const float* b2hh = (const float*)d_in[16];
    const float* bn2g = (const float*)d_in[17];
    const float* bn2b = (const float*)d_in[18];
    float* out = (float*)d_out;

    float *h1,*c1,*gates,*last,*cat,*xp2,*ph,*pc,*hin,*cin,*bs1,*bs2,*mu,*rstd;
    int *map32;
    cudaGetSymbolAddress((void**)&h1,   g_h1);
    cudaGetSymbolAddress((void**)&c1,   g_c1);
    cudaGetSymbolAddress((void**)&gates,g_gates);
    cudaGetSymbolAddress((void**)&last, g_last);
    cudaGetSymbolAddress((void**)&cat,  g_cat);
    cudaGetSymbolAddress((void**)&xp2,  g_xp2);
    cudaGetSymbolAddress((void**)&ph,   g_ph);
    cudaGetSymbolAddress((void**)&pc,   g_pc);
    cudaGetSymbolAddress((void**)&hin,  g_hin);
    cudaGetSymbolAddress((void**)&cin,  g_cin);
    cudaGetSymbolAddress((void**)&bs1,  g_bs1);
    cudaGetSymbolAddress((void**)&bs2,  g_bs2);
    cudaGetSymbolAddress((void**)&mu,   g_mu);
    cudaGetSymbolAddress((void**)&rstd, g_rstd);
    cudaGetSymbolAddress((void**)&map32, g_map32);

    // init
    cudaMemsetAsync(h1, 0, (size_t)BB*HID*4);
    cudaMemsetAsync(c1, 0, (size_t)BB*HID*4);
    cudaMemsetAsync(ph, 0, (size_t)(NN+1)*HID*4);
    cudaMemsetAsync(pc, 0, (size_t)(NN+1)*HID*4);
    cudaMemsetAsync(cin, 0, (size_t)NN*HID*4);
    vec_add2<<<(G4+255)/256, 256>>>(bs1, b1ih, b1hh, G4);
    vec_add2<<<(G4+255)/256, 256>>>(bs2, b2ih, b2hh, G4);

    // normalize mapping dtype (int64 vs int32) into int32 scratch
    detect_map<<<1, 32>>>((const long long*)mapping_raw);
    convert_map<<<(LL*NN*2 + 255)/256, 256>>>(mapping_raw, map32);

    dim3 blk(256);
    // ---- phase 1: LSTM1 over T steps ----
    dim3 g_big(G4/BN, BB/BM);   // (16, 128)
    long cellN1 = (long)BB * HID;
    int cellB1 = (int)((cellN1 + 255) / 256);
    for (int t = 0; t < TT; t++) {
        // gates = x_t @ W1ih^T + (bih+bhh)
        sgemm_bt<<<g_big, blk>>>(cond + (long)t * COND_D, TT*COND_D,
                                 W1ih, bs1, gates, BB, G4, COND_D, 0);
        // gates += h @ W1hh^T
        sgemm_bt<<<g_big, blk>>>(h1, HID, W1hh, nullptr, gates, BB, G4, HID, FLAG_ACC);
        lstm_cell1<<<cellB1, 256>>>(gates, h1, c1);
    }

    // ---- phase 2: cond linear + relu + BN1 ----
    dim3 g_cond(MID/BN, BB/BM);  // (2, 128)
    sgemm_bt<<<g_cond, blk>>>(h1, HID, condW, condb, last, BB, MID, HID, FLAG_RELU);
    bn_stats<<<MID/32, dim3(32,8)>>>(last, BB, MID, mu, rstd);
    {
        long tot = (long)BB * MID;
        bn_apply<<<(int)((tot+255)/256), 256>>>(last, mu, rstd, bn1g, bn1b, last, tot, MID);
    }

    // ---- phase 3: concat + xp2 GEMM ----
    {
        long tot = (long)BB * IN2;
        concat_in2<<<(int)((tot+255)/256), 256>>>(ops, extra, last, cat);
    }
    sgemm_bt<<<g_big, blk>>>(cat, IN2, W2ih, bs2, xp2, BB, G4, IN2, 0);

    // ---- phase 4: tree LSTM ----
    int cellB2 = (NN*HID + 255) / 256;
    dim3 g_tree(G4/BN, NN/BM);   // (16, 8)
    // first cell (idx = L-1): h_in = c_in = 0
    lstm_cell2<<<cellB2, 256>>>(xp2 + (long)(LL-1)*NN*G4, cin, ph, pc);
    for (int idx = LL - 2; idx >= 0; idx--) {
        gather_children<<<cellB2, 256>>>(map32 + idx*NN*2, ph, pc, hin, cin);
        sgemm_bt<<<g_tree, blk>>>(hin, HID, W2hh, nullptr,
                                  xp2 + (long)idx*NN*G4, NN, G4, HID, FLAG_ACC);
        lstm_cell2<<<cellB2, 256>>>(xp2 + (long)idx*NN*G4, cin, ph, pc);
    }

    // ---- phase 5: BN2 -> out ----
    bn_stats<<<HID/32, dim3(32,8)>>>(ph + HID, NN, HID, mu, rstd);
    {
        long tot = (long)NN * HID;
        bn_apply<<<(int)((tot+255)/256), 256>>>(ph + HID, mu, rstd, bn2g, bn2b, out, tot, HID);
    }
}

// round 5
// speedup vs baseline: 1.6035x; 1.6035x over previous
#include <cuda_runtime.h>
#include <cuda_bf16.h>
#include <cstdint>

// ---------------- problem constants ----------------
#define HID 512
#define MID 256
#define COND_D 256
#define OP_D 32
#define EX_D 32
#define LL 16
#define NN 1024
#define TT 8
#define BB (LL*NN)          // 16384
#define G4 (4*HID)          // 2048
#define IN2 (OP_D+EX_D+MID) // 320

// ---------------- scratch (device globals; no allocation allowed) ----------------
__device__ float g_h1[BB*HID];
__device__ float g_c1[BB*HID];
__device__ float g_gates[BB*G4];
__device__ float g_last[BB*MID];
__device__ float g_cat[BB*IN2];
__device__ float g_xp2[(long)BB*G4];
__device__ float g_ph[(NN+1)*HID];
__device__ float g_pc[(NN+1)*HID];
__device__ float g_hin[NN*HID];
__device__ float g_cin[NN*HID];
__device__ float g_bs1[G4];
__device__ float g_bs2[G4];
__device__ float g_mu[HID];
__device__ float g_rstd[HID];
__device__ int   g_map32[LL*NN*2];
__device__ int   g_map_is64;

// ---------------- low-level helpers ----------------
__device__ __forceinline__ uint32_t smem_u32(const void* p) {
    uint32_t a;
    asm("{ .reg .u64 t; cvta.to.shared.u64 t, %1; cvt.u32.u64 %0, t; }" : "=r"(a) : "l"(p));
    return a;
}
__device__ __forceinline__ void ldmx4(uint32_t* r, uint32_t addr) {
    asm volatile("ldmatrix.sync.aligned.m8n8.x4.shared.b16 {%0,%1,%2,%3}, [%4];"
        : "=r"(r[0]), "=r"(r[1]), "=r"(r[2]), "=r"(r[3]) : "r"(addr));
}
__device__ __forceinline__ void mma16816(float* d, const uint32_t* a, const uint32_t* b) {
    asm volatile("mma.sync.aligned.m16n8k16.row.col.f32.bf16.bf16.f32 "
        "{%0,%1,%2,%3}, {%4,%5,%6,%7}, {%8,%9}, {%0,%1,%2,%3};"
        : "+f"(d[0]), "+f"(d[1]), "+f"(d[2]), "+f"(d[3])
        : "r"(a[0]), "r"(a[1]), "r"(a[2]), "r"(a[3]), "r"(b[0]), "r"(b[1]));
}
// split two fp32 into packed bf16 hi-pair and lo-pair
__device__ __forceinline__ void split2(float x0, float x1, uint32_t& hi, uint32_t& lo) {
    __nv_bfloat16 h0 = __float2bfloat16(x0);
    __nv_bfloat16 h1 = __float2bfloat16(x1);
    __nv_bfloat16 l0 = __float2bfloat16(x0 - __bfloat162float(h0));
    __nv_bfloat16 l1 = __float2bfloat16(x1 - __bfloat162float(h1));
    union { __nv_bfloat16 b; unsigned short u; } u0, u1, v0, v1;
    u0.b = h0; u1.b = h1; v0.b = l0; v1.b = l1;
    hi = (uint32_t)u0.u | ((uint32_t)u1.u << 16);
    lo = (uint32_t)v0.u | ((uint32_t)v1.u << 16);
}

#define FLAG_RELU 2

// ---------------- mma.sync bf16-split GEMM ----------------
// C[M,N] = A1[M,K1]@B1[N,K1]^T (+ A2[M,K2]@B2[N,K2]^T) (+bias) (+addend) [relu]
// CTA tile 128x128, 8 warps (2m x 4n), warp tile 64x32, K chunk = 32.
// 3 mma passes per operand pair: Ahi*Bhi + Ahi*Blo + Alo*Bhi.
__global__ __launch_bounds__(256) void gemm_mma(
    const float* __restrict__ A1, int lda1, int K1, const float* __restrict__ B1,
    const float* __restrict__ A2, int lda2, int K2, const float* __restrict__ B2,
    const float* __restrict__ bias, const float* __restrict__ addend,
    float* __restrict__ C, int M, int N, int flags)
{
    __shared__ __align__(16) __nv_bfloat16 sAhi[128*32];
    __shared__ __align__(16) __nv_bfloat16 sAlo[128*32];
    __shared__ __align__(16) __nv_bfloat16 sBhi[128*32];
    __shared__ __align__(16) __nv_bfloat16 sBlo[128*32];

    int tid = threadIdx.x;
    int wid = tid >> 5, lane = tid & 31;
    int m0 = blockIdx.y * 128, n0 = blockIdx.x * 128;
    int wm = wid & 1, wn = wid >> 1;

    uint32_t uAhi = smem_u32(sAhi), uAlo = smem_u32(sAlo);
    uint32_t uBhi = smem_u32(sBhi), uBlo = smem_u32(sBlo);

    float acc[4][4][4];
    #pragma unroll
    for (int i = 0; i < 4; i++)
        #pragma unroll
        for (int j = 0; j < 4; j++)
            #pragma unroll
            for (int k = 0; k < 4; k++) acc[i][j][k] = 0.f;

    int nc1 = K1 / 32, nc2 = K2 / 32, ncT = nc1 + nc2;

    int r = tid >> 1;              // 0..127
    int khalf = (tid & 1) * 16;    // 0 or 16 within 32-chunk
    int c0 = (tid & 1) * 2;        // first 8-elem chunk index within row

    float4 stA[4], stB[4];

    // macro: load chunk ci's fp32 into staging regs
#define LOADC(ci) do { \
        int _ph = ((ci) >= nc1); \
        const float* _Ap = _ph ? A2 : A1; \
        const float* _Bp = _ph ? B2 : B1; \
        int _lda = _ph ? lda2 : lda1; \
        int _ldb = _ph ? K2 : K1; \
        int _k0 = (_ph ? (ci) - nc1 : (ci)) * 32 + khalf; \
        const float* _Ar = _Ap + (size_t)(m0 + r) * _lda + _k0; \
        const float* _Br = _Bp + (size_t)(n0 + r) * _ldb + _k0; \
        stA[0] = *(const float4*)(_Ar);      stA[1] = *(const float4*)(_Ar + 4); \
        stA[2] = *(const float4*)(_Ar + 8);  stA[3] = *(const float4*)(_Ar + 12); \
        stB[0] = *(const float4*)(_Br);      stB[1] = *(const float4*)(_Br + 4); \
        stB[2] = *(const float4*)(_Br + 8);  stB[3] = *(const float4*)(_Br + 12); \
    } while (0)

    // macro: convert staging regs -> swizzled bf16 smem
#define STOREC() do { \
        _Pragma("unroll") \
        for (int g = 0; g < 2; g++) { \
            int cb = c0 + g; \
            int off = r * 32 + ((cb ^ (r & 3)) * 8); \
            uint4 hi, lo; \
            split2(stA[2*g].x, stA[2*g].y, hi.x, lo.x); \
            split2(stA[2*g].z, stA[2*g].w, hi.y, lo.y); \
            split2(stA[2*g+1].x, stA[2*g+1].y, hi.z, lo.z); \
            split2(stA[2*g+1].z, stA[2*g+1].w, hi.w, lo.w); \
            *(uint4*)&sAhi[off] = hi; *(uint4*)&sAlo[off] = lo; \
            split2(stB[2*g].x, stB[2*g].y, hi.x, lo.x); \
            split2(stB[2*g].z, stB[2*g].w, hi.y, lo.y); \
            split2(stB[2*g+1].x, stB[2*g+1].y, hi.z, lo.z); \
            split2(stB[2*g+1].z, stB[2*g+1].w, hi.w, lo.w); \
            *(uint4*)&sBhi[off] = hi; *(uint4*)&sBlo[off] = lo; \
        } \
    } while (0)

    LOADC(0);
    STOREC();
    __syncthreads();

    for (int ci = 0; ci < ncT; ci++) {
        if (ci + 1 < ncT) LOADC(ci + 1);

        // compute chunk ci from smem: 2 k16 steps
        #pragma unroll
        for (int s = 0; s < 2; s++) {
            uint32_t ahi[4][4], alo[4][4];
            int acb = s * 2 + (lane >> 4);
            #pragma unroll
            for (int mt = 0; mt < 4; mt++) {
                int rr = wm * 64 + mt * 16 + (lane & 15);
                uint32_t boff = (uint32_t)(rr * 64 + ((acb ^ (rr & 3)) * 16));
                ldmx4(ahi[mt], uAhi + boff);
                ldmx4(alo[mt], uAlo + boff);
            }
            uint32_t bhi[4][2], blo[4][2];
            #pragma unroll
            for (int ntp = 0; ntp < 2; ntp++) {
                int rr = wn * 32 + ntp * 16 + (lane & 15);
                uint32_t boff = (uint32_t)(rr * 64 + ((acb ^ (rr & 3)) * 16));
                uint32_t t[4];
                ldmx4(t, uBhi + boff);
                bhi[2*ntp][0] = t[0]; bhi[2*ntp][1] = t[2];
                bhi[2*ntp+1][0] = t[1]; bhi[2*ntp+1][1] = t[3];
                ldmx4(t, uBlo + boff);
                blo[2*ntp][0] = t[0]; blo[2*ntp][1] = t[2];
                blo[2*ntp+1][0] = t[1]; blo[2*ntp+1][1] = t[3];
            }
            #pragma unroll
            for (int mt = 0; mt < 4; mt++)
                #pragma unroll
                for (int nt = 0; nt < 4; nt++) {
                    mma16816(acc[mt][nt], ahi[mt], bhi[nt]);
                    mma16816(acc[mt][nt], ahi[mt], blo[nt]);
                    mma16816(acc[mt][nt], alo[mt], bhi[nt]);
                }
        }
        __syncthreads();
        if (ci + 1 < ncT) {
            STOREC();
            __syncthreads();
        }
    }

    // epilogue
    #pragma unroll
    for (int mt = 0; mt < 4; mt++) {
        int row0 = m0 + wm * 64 + mt * 16 + (lane >> 2);
        #pragma unroll
        for (int nt = 0; nt < 4; nt++) {
            int col = n0 + wn * 32 + nt * 8 + (lane & 3) * 2;
            float* d = acc[mt][nt];
            float b0 = 0.f, b1 = 0.f;
            if (bias) { b0 = __ldg(bias + col); b1 = __ldg(bias + col + 1); }
            float v0 = d[0] + b0, v1 = d[1] + b1;
            float v2 = d[2] + b0, v3 = d[3] + b1;
            if (addend) {
                const float* Ad0 = addend + (size_t)row0 * N + col;
                const float* Ad1 = addend + (size_t)(row0 + 8) * N + col;
                v0 += Ad0[0]; v1 += Ad0[1];
                v2 += Ad1[0]; v3 += Ad1[1];
            }
            if (flags & FLAG_RELU) {
                v0 = fmaxf(v0, 0.f); v1 = fmaxf(v1, 0.f);
                v2 = fmaxf(v2, 0.f); v3 = fmaxf(v3, 0.f);
            }
            float* C0 = C + (size_t)row0 * N + col;
            float* C1 = C + (size_t)(row0 + 8) * N + col;
            C0[0] = v0; C0[1] = v1;
            C1[0] = v2; C1[1] = v3;
        }
    }
#undef LOADC
#undef STOREC
}

// ---------------- mapping dtype normalization ----------------
__global__ void detect_map(const long long* __restrict__ raw) {
    if (threadIdx.x == 0 && blockIdx.x == 0) {
        int ok = 1;
        for (int i = 0; i < 1024; i++) {
            long long v = raw[i];
            if (v < 0 || v > NN) { ok = 0; break; }
        }
        g_map_is64 = ok;
    }
}
__global__ void convert_map(const void* __restrict__ raw, int* __restrict__ o) {
    int i = blockIdx.x * blockDim.x + threadIdx.x;
    if (i >= LL*NN*2) return;
    if (g_map_is64) o[i] = (int)((const long long*)raw)[i];
    else            o[i] = ((const int*)raw)[i];
}

// ---------------- elementwise kernels ----------------
__device__ __forceinline__ float sigf(float x) { return 1.f / (1.f + expf(-x)); }

__global__ void vec_add2(float* o, const float* a, const float* b, int n) {
    int i = blockIdx.x * blockDim.x + threadIdx.x;
    if (i < n) o[i] = a[i] + b[i];
}

__global__ void lstm_cell1(const float* __restrict__ gates,
                           float* __restrict__ h, float* __restrict__ c) {
    long idx = (long)blockIdx.x * blockDim.x + threadIdx.x;
    if (idx >= (long)BB * HID) return;
    int b = (int)(idx >> 9), j = (int)(idx & 511);
    const float* g = gates + (long)b * G4;
    float ig = sigf(g[j]);
    float fg = sigf(g[HID + j]);
    float gg = tanhf(g[2*HID + j]);
    float og = sigf(g[3*HID + j]);
    float cn = fg * c[idx] + ig * gg;
    c[idx] = cn;
    h[idx] = og * tanhf(cn);
}

__global__ void lstm_cell2(const float* __restrict__ gates,
                           const float* __restrict__ cin,
                           float* __restrict__ ph, float* __restrict__ pc) {
    int idx = blockIdx.x * blockDim.x + threadIdx.x;
    if (idx >= NN * HID) return;
    int b = idx >> 9, j = idx & 511;
    const float* g = gates + (long)b * G4;
    float ig = sigf(g[j]);
    float fg = sigf(g[HID + j]);
    float gg = tanhf(g[2*HID + j]);
    float og = sigf(g[3*HID + j]);
    float cn = fg * cin[idx] + ig * gg;
    pc[(b + 1) * HID + j] = cn;
    ph[(b + 1) * HID + j] = og * tanhf(cn);
}

__global__ void gather_children(const int* __restrict__ mp,
                                const float* __restrict__ ph, const float* __restrict__ pc,
                                float* __restrict__ hin, float* __restrict__ cin) {
    int idx = blockIdx.x * blockDim.x + threadIdx.x;
    if (idx >= NN * HID) return;
    int n = idx >> 9, j = idx & 511;
    int a = mp[n*2 + 0];
    int b = mp[n*2 + 1];
    a = min(max(a, 0), NN);
    b = min(max(b, 0), NN);
    hin[idx] = 0.5f * (ph[a * HID + j] + ph[b * HID + j]);
    cin[idx] = 0.5f * (pc[a * HID + j] + pc[b * HID + j]);
}

__global__ void concat_in2(const float* __restrict__ ops, const float* __restrict__ ex,
                           const float* __restrict__ last, float* __restrict__ cat) {
    long idx = (long)blockIdx.x * blockDim.x + threadIdx.x;
    if (idx >= (long)BB * IN2) return;
    int r = (int)(idx / IN2), k = (int)(idx % IN2);
    float v;
    if (k < OP_D)            v = ops[(long)r * OP_D + k];
    else if (k < OP_D+EX_D)  v = ex[(long)r * EX_D + (k - OP_D)];
    else                     v = last[(long)r * MID + (k - OP_D - EX_D)];
    cat[idx] = v;
}

__global__ void bn_stats(const float* __restrict__ X, int Brows, int C,
                         float* __restrict__ mu, float* __restrict__ rstd) {
    int c = blockIdx.x * 32 + threadIdx.x;
    float s = 0.f, s2 = 0.f;
    for (int r = threadIdx.y; r < Brows; r += 8) {
        float v = X[(long)r * C + c];
        s += v; s2 += v * v;
    }
    __shared__ float sh[8][33], sh2[8][33];
    sh[threadIdx.y][threadIdx.x] = s;
    sh2[threadIdx.y][threadIdx.x] = s2;
    __syncthreads();
    if (threadIdx.y == 0) {
        #pragma unroll
        for (int y = 1; y < 8; y++) { s += sh[y][threadIdx.x]; s2 += sh2[y][threadIdx.x]; }
        float m = s / (float)Brows;
        float var = s2 / (float)Brows - m * m;
        mu[c] = m;
        rstd[c] = rsqrtf(var + 1e-5f);
    }
}

__global__ void bn_apply(const float* __restrict__ X,
                         const float* __restrict__ mu, const float* __restrict__ rstd,
                         const float* __restrict__ gam, const float* __restrict__ bet,
                         float* __restrict__ Y, long total, int C) {
    long idx = (long)blockIdx.x * blockDim.x + threadIdx.x;
    if (idx >= total) return;
    int c = (int)(idx % C);
    Y[idx] = gam[c] * (X[idx] - mu[c]) * rstd[c] + bet[c];
}

// ---------------- launch ----------------
extern "C" void kernel_launch(void* const* d_in, const int* in_sizes, int n_in,
                              void* d_out, int out_size) {
    const float* ops   = (const float*)d_in[0];
    const float* extra = (const float*)d_in[1];
    const float* cond  = (const float*)d_in[2];
    const void*  mapping_raw = d_in[4];
    const float* W1ih = (const float*)d_in[5];
    const float* W1hh = (const float*)d_in[6];
    const float* b1ih = (const float*)d_in[7];
    const float* b1hh = (const float*)d_in[8];
    const float* condW = (const float*)d_in[9];
    const float* condb = (const float*)d_in[10];
    const float* bn1g = (const float*)d_in[11];
    const float* bn1b = (const float*)d_in[12];
    const float* W2ih = (const float*)d_in[13];
    const float* W2hh = (const float*)d_in[14];
    const float* b2ih = (const float*)d_in[15];
    const float* b2hh = (const float*)d_in[16];
    const float* bn2g = (const float*)d_in[17];
    const float* bn2b = (const float*)d_in[18];
    float* out = (float*)d_out;

    float *h1,*c1,*gates,*last,*cat,*xp2,*ph,*pc,*hin,*cin,*bs1,*bs2,*mu,*rstd;
    int *map32;
    cudaGetSymbolAddress((void**)&h1,   g_h1);
    cudaGetSymbolAddress((void**)&c1,   g_c1);
    cudaGetSymbolAddress((void**)&gates,g_gates);
    cudaGetSymbolAddress((void**)&last, g_last);
    cudaGetSymbolAddress((void**)&cat,  g_cat);
    cudaGetSymbolAddress((void**)&xp2,  g_xp2);
    cudaGetSymbolAddress((void**)&ph,   g_ph);
    cudaGetSymbolAddress((void**)&pc,   g_pc);
    cudaGetSymbolAddress((void**)&hin,  g_hin);
    cudaGetSymbolAddress((void**)&cin,  g_cin);
    cudaGetSymbolAddress((void**)&bs1,  g_bs1);
    cudaGetSymbolAddress((void**)&bs2,  g_bs2);
    cudaGetSymbolAddress((void**)&mu,   g_mu);
    cudaGetSymbolAddress((void**)&rstd, g_rstd);
    cudaGetSymbolAddress((void**)&map32, g_map32);

    // init
    cudaMemsetAsync(c1, 0, (size_t)BB*HID*4);
    cudaMemsetAsync(ph, 0, (size_t)(NN+1)*HID*4);
    cudaMemsetAsync(pc, 0, (size_t)(NN+1)*HID*4);
    cudaMemsetAsync(cin, 0, (size_t)NN*HID*4);
    vec_add2<<<(G4+255)/256, 256>>>(bs1, b1ih, b1hh, G4);
    vec_add2<<<(G4+255)/256, 256>>>(bs2, b2ih, b2hh, G4);
    detect_map<<<1, 32>>>((const long long*)mapping_raw);
    convert_map<<<(LL*NN*2 + 255)/256, 256>>>(mapping_raw, map32);

    // ---- phase 1: LSTM1 over T steps (x-proj + h-proj fused into one GEMM) ----
    dim3 g_big(G4/128, BB/128);   // (16, 128)
    long cellN1 = (long)BB * HID;
    int cellB1 = (int)((cellN1 + 255) / 256);
    for (int t = 0; t < TT; t++) {
        gemm_mma<<<g_big, 256>>>(
            cond + (long)t * COND_D, TT*COND_D, COND_D, W1ih,
            h1, HID, (t == 0) ? 0 : HID, W1hh,
            bs1, nullptr, gates, BB, G4, 0);
        lstm_cell1<<<cellB1, 256>>>(gates, h1, c1);
    }

    // ---- phase 2: cond linear + relu + BN1 ----
    dim3 g_cond(MID/128, BB/128);
    gemm_mma<<<g_cond, 256>>>(
        h1, HID, HID, condW, nullptr, 0, 0, nullptr,
        condb, nullptr, last, BB, MID, FLAG_RELU);
    bn_stats<<<MID/32, dim3(32,8)>>>(last, BB, MID, mu, rstd);
    {
        long tot = (long)BB * MID;
        bn_apply<<<(int)((tot+255)/256), 256>>>(last, mu, rstd, bn1g, bn1b, last, tot, MID);
    }

    // ---- phase 3: concat + xp2 GEMM ----
    {
        long tot = (long)BB * IN2;
        concat_in2<<<(int)((tot+255)/256), 256>>>(ops, extra, last, cat);
    }
    gemm_mma<<<g_big, 256>>>(
        cat, IN2, IN2, W2ih, nullptr, 0, 0, nullptr,
        bs2, nullptr, xp2, BB, G4, 0);

    // ---- phase 4: tree LSTM ----
    int cellB2 = (NN*HID + 255) / 256;
    dim3 g_tree(G4/128, NN/128);  // (16, 8)
    lstm_cell2<<<cellB2, 256>>>(xp2 + (long)(LL-1)*NN*G4, cin, ph, pc);
    for (int idx = LL - 2; idx >= 0; idx--) {
        gather_children<<<cellB2, 256>>>(map32 + idx*NN*2, ph, pc, hin, cin);
        gemm_mma<<<g_tree, 256>>>(
            hin, HID, HID, W2hh, nullptr, 0, 0, nullptr,
            nullptr, xp2 + (long)idx*NN*G4, gates, NN, G4, 0);
        lstm_cell2<<<cellB2, 256>>>(gates, cin, ph, pc);
    }

    // ---- phase 5: BN2 -> out ----
    bn_stats<<<HID/32, dim3(32,8)>>>(ph + HID, NN, HID, mu, rstd);
    {
        long tot = (long)NN * HID;
        bn_apply<<<(int)((tot+255)/256), 256>>>(ph + HID, mu, rstd, bn2g, bn2b, out, tot, HID);
    }
}

// round 7
// speedup vs baseline: 1.9795x; 1.2345x over previous
#include <cuda_runtime.h>
#include <cuda_bf16.h>
#include <cstdint>

// ---------------- problem constants ----------------
#define HID 512
#define MID 256
#define COND_D 256
#define OP_D 32
#define EX_D 32
#define LL 16
#define NN 1024
#define TT 8
#define BB (LL*NN)          // 16384
#define G4 (4*HID)          // 2048
#define IN2 (OP_D+EX_D+MID) // 320

// ---------------- scratch (device globals; no allocation allowed) ----------------
__device__ __align__(16) __nv_bfloat16 g_h1hi[BB*HID];
__device__ __align__(16) __nv_bfloat16 g_h1lo[BB*HID];
__device__ float g_c1[BB*HID];
__device__ float g_gates[BB*G4];
__device__ float g_last[BB*MID];
__device__ __align__(16) __nv_bfloat16 g_cathi[BB*IN2];
__device__ __align__(16) __nv_bfloat16 g_catlo[BB*IN2];
__device__ float g_xp2[(long)BB*G4];
__device__ float g_ph[(NN+1)*HID];
__device__ float g_pc[(NN+1)*HID];
__device__ __align__(16) __nv_bfloat16 g_hinhi[NN*HID];
__device__ __align__(16) __nv_bfloat16 g_hinlo[NN*HID];
__device__ float g_cin[NN*HID];
__device__ float g_bs1[G4];
__device__ float g_bs2[G4];
__device__ float g_mu[HID];
__device__ float g_rstd[HID];
__device__ int   g_map32[LL*NN*2];
__device__ int   g_map_is64;
// weight / input splits
__device__ __align__(16) __nv_bfloat16 g_w1ih_hi[G4*COND_D];
__device__ __align__(16) __nv_bfloat16 g_w1ih_lo[G4*COND_D];
__device__ __align__(16) __nv_bfloat16 g_w1hh_hi[G4*HID];
__device__ __align__(16) __nv_bfloat16 g_w1hh_lo[G4*HID];
__device__ __align__(16) __nv_bfloat16 g_condw_hi[MID*HID];
__device__ __align__(16) __nv_bfloat16 g_condw_lo[MID*HID];
__device__ __align__(16) __nv_bfloat16 g_w2ih_hi[G4*IN2];
__device__ __align__(16) __nv_bfloat16 g_w2ih_lo[G4*IN2];
__device__ __align__(16) __nv_bfloat16 g_w2hh_hi[G4*HID];
__device__ __align__(16) __nv_bfloat16 g_w2hh_lo[G4*HID];
__device__ __align__(16) __nv_bfloat16 g_cond_hi[(long)BB*TT*COND_D];
__device__ __align__(16) __nv_bfloat16 g_cond_lo[(long)BB*TT*COND_D];

// ---------------- low-level helpers ----------------
__device__ __forceinline__ uint32_t smem_u32(const void* p) {
    uint32_t a;
    asm("{ .reg .u64 t; cvta.to.shared.u64 t, %1; cvt.u32.u64 %0, t; }" : "=r"(a) : "l"(p));
    return a;
}
__device__ __forceinline__ void ldmx4(uint32_t* r, uint32_t addr) {
    asm volatile("ldmatrix.sync.aligned.m8n8.x4.shared.b16 {%0,%1,%2,%3}, [%4];"
        : "=r"(r[0]), "=r"(r[1]), "=r"(r[2]), "=r"(r[3]) : "r"(addr));
}
__device__ __forceinline__ void mma16816(float* d, const uint32_t* a, const uint32_t* b) {
    asm volatile("mma.sync.aligned.m16n8k16.row.col.f32.bf16.bf16.f32 "
        "{%0,%1,%2,%3}, {%4,%5,%6,%7}, {%8,%9}, {%0,%1,%2,%3};"
        : "+f"(d[0]), "+f"(d[1]), "+f"(d[2]), "+f"(d[3])
        : "r"(a[0]), "r"(a[1]), "r"(a[2]), "r"(a[3]), "r"(b[0]), "r"(b[1]));
}
#define CPASYNC16(dst, src) asm volatile("cp.async.cg.shared.global [%0], [%1], 16;" :: "r"(dst), "l"(src))
#define CP_COMMIT() asm volatile("cp.async.commit_group;" ::: "memory")
#define CP_WAIT1()  asm volatile("cp.async.wait_group 1;" ::: "memory")
#define CP_WAIT0()  asm volatile("cp.async.wait_group 0;" ::: "memory")

__device__ __forceinline__ void split1(float x, __nv_bfloat16& hi, __nv_bfloat16& lo) {
    hi = __float2bfloat16(x);
    lo = __float2bfloat16(x - __bfloat162float(hi));
}

#define FLAG_RELU 2

// ---------------- mma.sync bf16-split GEMM (pre-split operands, cp.async double-buffer) ----
// C[M,N] = A1@B1^T (+ A2@B2^T) (+bias) (+addend) [relu]
// A/B given as bf16 hi/lo pairs. CTA tile 128x128, 8 warps (2m x 4n), K chunk = 64.
// 3 passes: Ahi*Bhi + Ahi*Blo + Alo*Bhi.
#define TSZ   16384           // one 128x64 bf16 tile
#define OFF_AH 0
#define OFF_AL TSZ
#define OFF_BH (2*TSZ)
#define OFF_BL (3*TSZ)
#define BUFSZ  (4*TSZ)        // 64 KB per stage
#define SMEM_TOTAL (2*BUFSZ)  // 128 KB

__global__ __launch_bounds__(256) void gemm_mma(
    const __nv_bfloat16* __restrict__ Ahi1, const __nv_bfloat16* __restrict__ Alo1, int lda1, int K1,
    const __nv_bfloat16* __restrict__ Bhi1, const __nv_bfloat16* __restrict__ Blo1,
    const __nv_bfloat16* __restrict__ Ahi2, const __nv_bfloat16* __restrict__ Alo2, int lda2, int K2,
    const __nv_bfloat16* __restrict__ Bhi2, const __nv_bfloat16* __restrict__ Blo2,
    const float* __restrict__ bias, const float* __restrict__ addend,
    float* __restrict__ C, int M, int N, int flags)
{
    extern __shared__ char smem[];
    uint32_t sb = smem_u32(smem);

    int tid = threadIdx.x;
    int wid = tid >> 5, lane = tid & 31;
    int m0 = blockIdx.y * 128, n0 = blockIdx.x * 128;
    int wm = wid & 1, wn = wid >> 1;

    float acc[4][4][4];
    #pragma unroll
    for (int i = 0; i < 4; i++)
        #pragma unroll
        for (int j = 0; j < 4; j++)
            #pragma unroll
            for (int k = 0; k < 4; k++) acc[i][j][k] = 0.f;

    int nc1 = K1 / 64, nc2 = K2 / 64, ncT = nc1 + nc2;

    int r = tid >> 1;            // 0..127 tile row
    int half = tid & 1;          // which 32-elem half of the 64-elem row

    // issue cp.async for chunk ci into buffer buf
    auto issue = [&](int ci, int buf) {
        int ph2 = (ci >= nc1);
        const __nv_bfloat16* Ah = ph2 ? Ahi2 : Ahi1;
        const __nv_bfloat16* Al = ph2 ? Alo2 : Alo1;
        const __nv_bfloat16* Bh = ph2 ? Bhi2 : Bhi1;
        const __nv_bfloat16* Bl = ph2 ? Blo2 : Blo1;
        int lda = ph2 ? lda2 : lda1;
        int ldb = ph2 ? K2 : K1;
        int k0 = (ci - (ph2 ? nc1 : 0)) * 64 + half * 32;
        const __nv_bfloat16* pAh = Ah + (size_t)(m0 + r) * lda + k0;
        const __nv_bfloat16* pAl = Al + (size_t)(m0 + r) * lda + k0;
        const __nv_bfloat16* pBh = Bh + (size_t)(n0 + r) * ldb + k0;
        const __nv_bfloat16* pBl = Bl + (size_t)(n0 + r) * ldb + k0;
        uint32_t base = sb + buf * BUFSZ;
        #pragma unroll
        for (int g = 0; g < 4; g++) {
            uint32_t doff = (uint32_t)(r * 128 + (((half * 4 + g) ^ (r & 7)) * 16));
            CPASYNC16(base + OFF_AH + doff, pAh + g * 8);
            CPASYNC16(base + OFF_AL + doff, pAl + g * 8);
            CPASYNC16(base + OFF_BH + doff, pBh + g * 8);
            CPASYNC16(base + OFF_BL + doff, pBl + g * 8);
        }
    };

    issue(0, 0);
    CP_COMMIT();

    for (int ci = 0; ci < ncT; ci++) {
        if (ci + 1 < ncT) {
            issue(ci + 1, (ci + 1) & 1);
            CP_COMMIT();
            CP_WAIT1();
        } else {
            CP_WAIT0();
        }
        __syncthreads();

        uint32_t base = sb + (ci & 1) * BUFSZ;
        #pragma unroll
        for (int s = 0; s < 4; s++) {
            uint32_t ahi[4][4], alo[4][4];
            #pragma unroll
            for (int mt = 0; mt < 4; mt++) {
                int rr = wm * 64 + mt * 16 + (lane & 15);
                int g = (s * 2 + (lane >> 4)) ^ (rr & 7);
                uint32_t boff = (uint32_t)(rr * 128 + g * 16);
                ldmx4(ahi[mt], base + OFF_AH + boff);
                ldmx4(alo[mt], base + OFF_AL + boff);
            }
            uint32_t bhi[4][2], blo[4][2];
            #pragma unroll
            for (int ntp = 0; ntp < 2; ntp++) {
                int rr = wn * 32 + ntp * 16 + (lane & 15);
                int g = (s * 2 + (lane >> 4)) ^ (rr & 7);
                uint32_t boff = (uint32_t)(rr * 128 + g * 16);
                uint32_t t[4];
                ldmx4(t, base + OFF_BH + boff);
                bhi[2*ntp][0] = t[0]; bhi[2*ntp][1] = t[2];
                bhi[2*ntp+1][0] = t[1]; bhi[2*ntp+1][1] = t[3];
                ldmx4(t, base + OFF_BL + boff);
                blo[2*ntp][0] = t[0]; blo[2*ntp][1] = t[2];
                blo[2*ntp+1][0] = t[1]; blo[2*ntp+1][1] = t[3];
            }
            #pragma unroll
            for (int mt = 0; mt < 4; mt++)
                #pragma unroll
                for (int nt = 0; nt < 4; nt++) {
                    mma16816(acc[mt][nt], ahi[mt], bhi[nt]);
                    mma16816(acc[mt][nt], ahi[mt], blo[nt]);
                    mma16816(acc[mt][nt], alo[mt], bhi[nt]);
                }
        }
        __syncthreads();
    }

    // epilogue
    #pragma unroll
    for (int mt = 0; mt < 4; mt++) {
        int row0 = m0 + wm * 64 + mt * 16 + (lane >> 2);
        #pragma unroll
        for (int nt = 0; nt < 4; nt++) {
            int col = n0 + wn * 32 + nt * 8 + (lane & 3) * 2;
            float* d = acc[mt][nt];
            float b0 = 0.f, b1 = 0.f;
            if (bias) { b0 = __ldg(bias + col); b1 = __ldg(bias + col + 1); }
            float v0 = d[0] + b0, v1 = d[1] + b1;
            float v2 = d[2] + b0, v3 = d[3] + b1;
            if (addend) {
                const float* Ad0 = addend + (size_t)row0 * N + col;
                const float* Ad1 = addend + (size_t)(row0 + 8) * N + col;
                v0 += Ad0[0]; v1 += Ad0[1];
                v2 += Ad1[0]; v3 += Ad1[1];
            }
            if (flags & FLAG_RELU) {
                v0 = fmaxf(v0, 0.f); v1 = fmaxf(v1, 0.f);
                v2 = fmaxf(v2, 0.f); v3 = fmaxf(v3, 0.f);
            }
            float* C0 = C + (size_t)row0 * N + col;
            float* C1 = C + (size_t)(row0 + 8) * N + col;
            C0[0] = v0; C0[1] = v1;
            C1[0] = v2; C1[1] = v3;
        }
    }
}

// ---------------- split kernel: fp32 -> bf16 hi/lo ----------------
__global__ void split_arr(const float* __restrict__ x,
                          __nv_bfloat16* __restrict__ hi, __nv_bfloat16* __restrict__ lo,
                          long n) {
    long i = (long)blockIdx.x * blockDim.x + threadIdx.x;
    if (i >= n) return;
    split1(x[i], hi[i], lo[i]);
}

// ---------------- mapping dtype normalization ----------------
__global__ void detect_map(const long long* __restrict__ raw) {
    if (threadIdx.x == 0 && blockIdx.x == 0) {
        int ok = 1;
        for (int i = 0; i < 1024; i++) {
            long long v = raw[i];
            if (v < 0 || v > NN) { ok = 0; break; }
        }
        g_map_is64 = ok;
    }
}
__global__ void convert_map(const void* __restrict__ raw, int* __restrict__ o) {
    int i = blockIdx.x * blockDim.x + threadIdx.x;
    if (i >= LL*NN*2) return;
    if (g_map_is64) o[i] = (int)((const long long*)raw)[i];
    else            o[i] = ((const int*)raw)[i];
}

// ---------------- elementwise kernels ----------------
__device__ __forceinline__ float sigf(float x) { return 1.f / (1.f + expf(-x)); }

__global__ void vec_add2(float* o, const float* a, const float* b, int n) {
    int i = blockIdx.x * blockDim.x + threadIdx.x;
    if (i < n) o[i] = a[i] + b[i];
}

// phase-1 cell: h written as bf16 hi/lo split, c stays fp32
__global__ void lstm_cell1(const float* __restrict__ gates,
                           __nv_bfloat16* __restrict__ hhi, __nv_bfloat16* __restrict__ hlo,
                           float* __restrict__ c) {
    long idx = (long)blockIdx.x * blockDim.x + threadIdx.x;
    if (idx >= (long)BB * HID) return;
    int b = (int)(idx >> 9), j = (int)(idx & 511);
    const float* g = gates + (long)b * G4;
    float ig = sigf(g[j]);
    float fg = sigf(g[HID + j]);
    float gg = tanhf(g[2*HID + j]);
    float og = sigf(g[3*HID + j]);
    float cn = fg * c[idx] + ig * gg;
    c[idx] = cn;
    float h = og * tanhf(cn);
    split1(h, hhi[idx], hlo[idx]);
}

__global__ void lstm_cell2(const float* __restrict__ gates,
                           const float* __restrict__ cin,
                           float* __restrict__ ph, float* __restrict__ pc) {
    int idx = blockIdx.x * blockDim.x + threadIdx.x;
    if (idx >= NN * HID) return;
    int b = idx >> 9, j = idx & 511;
    const float* g = gates + (long)b * G4;
    float ig = sigf(g[j]);
    float fg = sigf(g[HID + j]);
    float gg = tanhf(g[2*HID + j]);
    float og = sigf(g[3*HID + j]);
    float cn = fg * cin[idx] + ig * gg;
    pc[(b + 1) * HID + j] = cn;
    ph[(b + 1) * HID + j] = og * tanhf(cn);
}

// children gather: hin (split bf16) and cin (fp32)
__global__ void gather_children(const int* __restrict__ mp,
                                const float* __restrict__ ph, const float* __restrict__ pc,
                                __nv_bfloat16* __restrict__ hinhi, __nv_bfloat16* __restrict__ hinlo,
                                float* __restrict__ cin) {
    int idx = blockIdx.x * blockDim.x + threadIdx.x;
    if (idx >= NN * HID) return;
    int n = idx >> 9, j = idx & 511;
    int a = mp[n*2 + 0];
    int b = mp[n*2 + 1];
    a = min(max(a, 0), NN);
    b = min(max(b, 0), NN);
    float hv = 0.5f * (ph[a * HID + j] + ph[b * HID + j]);
    split1(hv, hinhi[idx], hinlo[idx]);
    cin[idx] = 0.5f * (pc[a * HID + j] + pc[b * HID + j]);
}

// concat [ops | extra | last] -> split bf16 cat [BB, 320]
__global__ void concat_in2(const float* __restrict__ ops, const float* __restrict__ ex,
                           const float* __restrict__ last,
                           __nv_bfloat16* __restrict__ chi, __nv_bfloat16* __restrict__ clo) {
    long idx = (long)blockIdx.x * blockDim.x + threadIdx.x;
    if (idx >= (long)BB * IN2) return;
    int r = (int)(idx / IN2), k = (int)(idx % IN2);
    float v;
    if (k < OP_D)            v = ops[(long)r * OP_D + k];
    else if (k < OP_D+EX_D)  v = ex[(long)r * EX_D + (k - OP_D)];
    else                     v = last[(long)r * MID + (k - OP_D - EX_D)];
    split1(v, chi[idx], clo[idx]);
}

__global__ void bn_stats(const float* __restrict__ X, int Brows, int C,
                         float* __restrict__ mu, float* __restrict__ rstd) {
    int c = blockIdx.x * 32 + threadIdx.x;
    float s = 0.f, s2 = 0.f;
    for (int r = threadIdx.y; r < Brows; r += 8) {
        float v = X[(long)r * C + c];
        s += v; s2 += v * v;
    }
    __shared__ float sh[8][33], sh2[8][33];
    sh[threadIdx.y][threadIdx.x] = s;
    sh2[threadIdx.y][threadIdx.x] = s2;
    __syncthreads();
    if (threadIdx.y == 0) {
        #pragma unroll
        for (int y = 1; y < 8; y++) { s += sh[y][threadIdx.x]; s2 += sh2[y][threadIdx.x]; }
        float m = s / (float)Brows;
        float var = s2 / (float)Brows - m * m;
        mu[c] = m;
        rstd[c] = rsqrtf(var + 1e-5f);
    }
}

__global__ void bn_apply(const float* __restrict__ X,
                         const float* __restrict__ mu, const float* __restrict__ rstd,
                         const float* __restrict__ gam, const float* __restrict__ bet,
                         float* __restrict__ Y, long total, int C) {
    long idx = (long)blockIdx.x * blockDim.x + threadIdx.x;
    if (idx >= total) return;
    int c = (int)(idx % C);
    Y[idx] = gam[c] * (X[idx] - mu[c]) * rstd[c] + bet[c];
}

// ---------------- launch ----------------
extern "C" void kernel_launch(void* const* d_in, const int* in_sizes, int n_in,
                              void* d_out, int out_size) {
    const float* ops   = (const float*)d_in[0];
    const float* extra = (const float*)d_in[1];
    const float* cond  = (const float*)d_in[2];
    const void*  mapping_raw = d_in[4];
    const float* W1ih = (const float*)d_in[5];
    const float* W1hh = (const float*)d_in[6];
    const float* b1ih = (const float*)d_in[7];
    const float* b1hh = (const float*)d_in[8];
    const float* condW = (const float*)d_in[9];
    const float* condb = (const float*)d_in[10];
    const float* bn1g = (const float*)d_in[11];
    const float* bn1b = (const float*)d_in[12];
    const float* W2ih = (const float*)d_in[13];
    const float* W2hh = (const float*)d_in[14];
    const float* b2ih = (const float*)d_in[15];
    const float* b2hh = (const float*)d_in[16];
    const float* bn2g = (const float*)d_in[17];
    const float* bn2b = (const float*)d_in[18];
    float* out = (float*)d_out;

    float *c1,*gates,*last,*xp2,*ph,*pc,*cin,*bs1,*bs2,*mu,*rstd;
    __nv_bfloat16 *h1hi,*h1lo,*cathi,*catlo,*hinhi,*hinlo;
    __nv_bfloat16 *w1ih_hi,*w1ih_lo,*w1hh_hi,*w1hh_lo,*condw_hi,*condw_lo;
    __nv_bfloat16 *w2ih_hi,*w2ih_lo,*w2hh_hi,*w2hh_lo,*cond_hi,*cond_lo;
    int *map32;
    cudaGetSymbolAddress((void**)&h1hi, g_h1hi);
    cudaGetSymbolAddress((void**)&h1lo, g_h1lo);
    cudaGetSymbolAddress((void**)&c1,   g_c1);
    cudaGetSymbolAddress((void**)&gates,g_gates);
    cudaGetSymbolAddress((void**)&last, g_last);
    cudaGetSymbolAddress((void**)&cathi,g_cathi);
    cudaGetSymbolAddress((void**)&catlo,g_catlo);
    cudaGetSymbolAddress((void**)&xp2,  g_xp2);
    cudaGetSymbolAddress((void**)&ph,   g_ph);
    cudaGetSymbolAddress((void**)&pc,   g_pc);
    cudaGetSymbolAddress((void**)&hinhi,g_hinhi);
    cudaGetSymbolAddress((void**)&hinlo,g_hinlo);
    cudaGetSymbolAddress((void**)&cin,  g_cin);
    cudaGetSymbolAddress((void**)&bs1,  g_bs1);
    cudaGetSymbolAddress((void**)&bs2,  g_bs2);
    cudaGetSymbolAddress((void**)&mu,   g_mu);
    cudaGetSymbolAddress((void**)&rstd, g_rstd);
    cudaGetSymbolAddress((void**)&map32, g_map32);
    cudaGetSymbolAddress((void**)&w1ih_hi, g_w1ih_hi);
    cudaGetSymbolAddress((void**)&w1ih_lo, g_w1ih_lo);
    cudaGetSymbolAddress((void**)&w1hh_hi, g_w1hh_hi);
    cudaGetSymbolAddress((void**)&w1hh_lo, g_w1hh_lo);
    cudaGetSymbolAddress((void**)&condw_hi, g_condw_hi);
    cudaGetSymbolAddress((void**)&condw_lo, g_condw_lo);
    cudaGetSymbolAddress((void**)&w2ih_hi, g_w2ih_hi);
    cudaGetSymbolAddress((void**)&w2ih_lo, g_w2ih_lo);
    cudaGetSymbolAddress((void**)&w2hh_hi, g_w2hh_hi);
    cudaGetSymbolAddress((void**)&w2hh_lo, g_w2hh_lo);
    cudaGetSymbolAddress((void**)&cond_hi, g_cond_hi);
    cudaGetSymbolAddress((void**)&cond_lo, g_cond_lo);

    cudaFuncSetAttribute(gemm_mma, cudaFuncAttributeMaxDynamicSharedMemorySize, SMEM_TOTAL);

    // init
    cudaMemsetAsync(c1, 0, (size_t)BB*HID*4);
    cudaMemsetAsync(ph, 0, (size_t)(NN+1)*HID*4);
    cudaMemsetAsync(pc, 0, (size_t)(NN+1)*HID*4);
    cudaMemsetAsync(cin, 0, (size_t)NN*HID*4);
    vec_add2<<<(G4+255)/256, 256>>>(bs1, b1ih, b1hh, G4);
    vec_add2<<<(G4+255)/256, 256>>>(bs2, b2ih, b2hh, G4);
    detect_map<<<1, 32>>>((const long long*)mapping_raw);
    convert_map<<<(LL*NN*2 + 255)/256, 256>>>(mapping_raw, map32);

    // one-time splits: weights + cond
    auto SPL = [](const float* x, __nv_bfloat16* hi, __nv_bfloat16* lo, long n) {
        split_arr<<<(int)((n + 255) / 256), 256>>>(x, hi, lo, n);
    };
    SPL(W1ih, w1ih_hi, w1ih_lo, (long)G4*COND_D);
    SPL(W1hh, w1hh_hi, w1hh_lo, (long)G4*HID);
    SPL(condW, condw_hi, condw_lo, (long)MID*HID);
    SPL(W2ih, w2ih_hi, w2ih_lo, (long)G4*IN2);
    SPL(W2hh, w2hh_hi, w2hh_lo, (long)G4*HID);
    SPL(cond, cond_hi, cond_lo, (long)BB*TT*COND_D);

    // ---- phase 1: LSTM1 over T steps (x-proj + h-proj fused into one GEMM) ----
    dim3 g_big(G4/128, BB/128);   // (16, 128)
    long cellN1 = (long)BB * HID;
    int cellB1 = (int)((cellN1 + 255) / 256);
    for (int t = 0; t < TT; t++) {
        gemm_mma<<<g_big, 256, SMEM_TOTAL>>>(
            cond_hi + (long)t * COND_D, cond_lo + (long)t * COND_D, TT*COND_D, COND_D,
            w1ih_hi, w1ih_lo,
            h1hi, h1lo, HID, (t == 0) ? 0 : HID, w1hh_hi, w1hh_lo,
            bs1, nullptr, gates, BB, G4, 0);
        lstm_cell1<<<cellB1, 256>>>(gates, h1hi, h1lo, c1);
    }

    // ---- phase 2: cond linear + relu + BN1 ----
    dim3 g_cond(MID/128, BB/128);
    gemm_mma<<<g_cond, 256, SMEM_TOTAL>>>(
        h1hi, h1lo, HID, HID, condw_hi, condw_lo,
        nullptr, nullptr, 0, 0, nullptr, nullptr,
        condb, nullptr, last, BB, MID, FLAG_RELU);
    bn_stats<<<MID/32, dim3(32,8)>>>(last, BB, MID, mu, rstd);
    {
        long tot = (long)BB * MID;
        bn_apply<<<(int)((tot+255)/256), 256>>>(last, mu, rstd, bn1g, bn1b, last, tot, MID);
    }

    // ---- phase 3: concat(split) + xp2 GEMM ----
    {
        long tot = (long)BB * IN2;
        concat_in2<<<(int)((tot+255)/256), 256>>>(ops, extra, last, cathi, catlo);
    }
    gemm_mma<<<g_big, 256, SMEM_TOTAL>>>(
        cathi, catlo, IN2, IN2, w2ih_hi, w2ih_lo,
        nullptr, nullptr, 0, 0, nullptr, nullptr,
        bs2, nullptr, xp2, BB, G4, 0);

    // ---- phase 4: tree LSTM ----
    int cellB2 = (NN*HID + 255) / 256;
    dim3 g_tree(G4/128, NN/128);  // (16, 8)
    lstm_cell2<<<cellB2, 256>>>(xp2 + (long)(LL-1)*NN*G4, cin, ph, pc);
    for (int idx = LL - 2; idx >= 0; idx--) {
        gather_children<<<cellB2, 256>>>(map32 + idx*NN*2, ph, pc, hinhi, hinlo, cin);
        gemm_mma<<<g_tree, 256, SMEM_TOTAL>>>(
            hinhi, hinlo, HID, HID, w2hh_hi, w2hh_lo,
            nullptr, nullptr, 0, 0, nullptr, nullptr,
            nullptr, xp2 + (long)idx*NN*G4, gates, NN, G4, 0);
        lstm_cell2<<<cellB2, 256>>>(gates, cin, ph, pc);
    }

    // ---- phase 5: BN2 -> out ----
    bn_stats<<<HID/32, dim3(32,8)>>>(ph + HID, NN, HID, mu, rstd);
    {
        long tot = (long)NN * HID;
        bn_apply<<<(int)((tot+255)/256), 256>>>(ph + HID, mu, rstd, bn2g, bn2b, out, tot, HID);
    }
}